// round 5
// baseline (speedup 1.0000x reference)
#include <cuda_runtime.h>

// ActorNetwork_mid_concat: 7 sequential tiny-MLP evaluations with argmax-driven
// state updates. Persistent 16-block kernel; w3 (128x2048) partitioned into
// 16 register-resident 128x128 slices; barrier-free cross-block partial
// exchange via monotonic flags (graph-replay safe, no reset needed).

#define NBLK  16
#define NTHR  256
#define NSTEP 7

// Persistent device scratch (allowed: no allocation).
__device__ float g_partial[2][NBLK][128];
__device__ volatile unsigned g_flag[NBLK];   // cumulative step count per block (monotonic across launches)

__global__ __launch_bounds__(NTHR, 1)
void actor_net_kernel(const float* __restrict__ inp,
                      const float* __restrict__ conv_w, const float* __restrict__ conv_b,
                      const float* __restrict__ w0, const float* __restrict__ b0,
                      const float* __restrict__ w1, const float* __restrict__ b1,
                      const float* __restrict__ w2, const float* __restrict__ b2,
                      const float* __restrict__ w3, const float* __restrict__ b3,
                      const float* __restrict__ w4, const float* __restrict__ b4,
                      float* __restrict__ out)
{
    __shared__ __align__(16) float feat[2048];
    __shared__ float cw[128 * 4], cb[128];
    __shared__ float w0s[128], b0s[128], w1s[128], b1s[128];
    __shared__ float w2s[128], b2s[128], b3s[128];
    __shared__ float w4s[6 * 128], b4s[6];
    __shared__ float st[6][8], bw[8], vcs[6];
    __shared__ float hbuf[128], lg[6];
    __shared__ unsigned sbase;

    const int tid = threadIdx.x;
    const int bid = blockIdx.x;

    // ---- Prologue: small weights + state into SMEM ----
    for (int i = tid; i < 512; i += NTHR) cw[i] = conv_w[i];
    if (tid < 128) {
        cb[tid]  = conv_b[tid];
        w0s[tid] = w0[tid];  b0s[tid] = b0[tid];
        w1s[tid] = w1[tid];  b1s[tid] = b1[tid];
        w2s[tid] = w2[tid];  b2s[tid] = b2[tid];
        b3s[tid] = b3[tid];
    }
    for (int i = tid; i < 768; i += NTHR) w4s[i] = w4[i];
    if (tid < 6)  b4s[tid] = b4[tid];
    if (tid < 48) st[tid >> 3][tid & 7] = inp[tid];
    if (tid >= 48 && tid < 56) bw[tid - 48] = inp[tid];
    if (tid < 6)  vcs[tid] = inp[56] * (float)(1 << tid);   // vs * {1,2,4,8,16,32}
    if (tid == 0) sbase = g_flag[bid];                       // stable: only we write it

    // ---- w3 slice -> registers: thread t holds row r = t>>1, 64 cols (half = t&1) ----
    const int r    = tid >> 1;
    const int half = tid & 1;
    float4 W[16];
    const float4* w3row =
        reinterpret_cast<const float4*>(w3 + (size_t)r * 2048 + bid * 128 + half * 64);
#pragma unroll
    for (int i = 0; i < 16; i++) W[i] = __ldg(&w3row[i]);

    __syncthreads();
    const unsigned base = sbase;

    for (int s = 0; s < NSTEP; ++s) {
        // ---- Phase A: build feat (2048) in SMEM ----
        if (tid < 128) {
            feat[tid]        = fmaxf(fmaf(st[0][7], w0s[tid], b0s[tid]), 0.0f);
            feat[1920 + tid] =       fmaf(st[4][7], w2s[tid], b2s[tid]);        // s5: no relu
        } else {
            const int f = tid - 128;
            feat[128 + f] = fmaxf(fmaf(st[1][7], w1s[f], b1s[f]), 0.0f);
        }
        // 13 conv windows x 128 filters
        for (int j = tid; j < 13 * 128; j += NTHR) {
            const int f = j / 13;
            const int w = j - f * 13;
            int row, k, dst;
            if (w < 5)       { row = 2; k = w;      dst = 256  + f * 5 + k; }
            else if (w < 10) { row = 3; k = w - 5;  dst = 896  + f * 5 + k; }
            else             { row = 4; k = w - 10; dst = 1536 + f * 3 + k; }
            float v = cb[f];
            v = fmaf(st[row][k],     cw[f * 4 + 0], v);
            v = fmaf(st[row][k + 1], cw[f * 4 + 1], v);
            v = fmaf(st[row][k + 2], cw[f * 4 + 2], v);
            v = fmaf(st[row][k + 3], cw[f * 4 + 3], v);
            feat[dst] = fmaxf(v, 0.0f);
        }
        __syncthreads();

        // ---- Phase B: register-resident partial matvec for this block's 128-col slice ----
        const float4* fp = reinterpret_cast<const float4*>(feat + bid * 128 + half * 64);
        float4 acc = make_float4(0.f, 0.f, 0.f, 0.f);
#pragma unroll
        for (int i = 0; i < 16; i++) {
            const float4 f4 = fp[i];
            acc.x = fmaf(W[i].x, f4.x, acc.x);
            acc.y = fmaf(W[i].y, f4.y, acc.y);
            acc.z = fmaf(W[i].z, f4.z, acc.z);
            acc.w = fmaf(W[i].w, f4.w, acc.w);
        }
        float p = (acc.x + acc.y) + (acc.z + acc.w);
        p += __shfl_xor_sync(0xffffffffu, p, 1);   // combine the two halves of row r

        const int buf = s & 1;
        if (half == 0) {
            __stcg(&g_partial[buf][bid][r], p);
            __threadfence();                        // release: partials visible before flag
        }
        __syncthreads();
        if (tid == 0) g_flag[bid] = base + (unsigned)s + 1u;   // volatile store

        // ---- Phase C: wait for all blocks' partials for this step ----
        const unsigned target = base + (unsigned)s + 1u;
        if (tid < NBLK) {
            while (g_flag[tid] < target) { /* spin on L2 */ }
            __threadfence();                        // acquire
        }
        __syncthreads();

        // ---- Phase D: deterministic reduce -> h (every block, identical order) ----
        if (tid < 128) {
            float a = b3s[tid];
#pragma unroll
            for (int b = 0; b < NBLK; b++) a += __ldcg(&g_partial[buf][b][tid]);
            hbuf[tid] = fmaxf(a, 0.0f);
        }
        __syncthreads();

        // ---- Phase E: logits = w4 @ h + b4 (6 warps) ----
        if (tid < 192) {
            const int a = tid >> 5, l = tid & 31;
            float v = 0.0f;
            v = fmaf(w4s[a * 128 + l],      hbuf[l],      v);
            v = fmaf(w4s[a * 128 + l + 32], hbuf[l + 32], v);
            v = fmaf(w4s[a * 128 + l + 64], hbuf[l + 64], v);
            v = fmaf(w4s[a * 128 + l + 96], hbuf[l + 96], v);
#pragma unroll
            for (int o = 16; o > 0; o >>= 1) v += __shfl_down_sync(0xffffffffu, v, o);
            if (l == 0) lg[a] = v + b4s[a];
        }
        __syncthreads();

        // ---- Phase F: argmax + state update (exact reference arithmetic) ----
        if (s < 6) {
            if (tid == 0) {
                int   a    = 0;
                float best = lg[0];
#pragma unroll
                for (int j = 1; j < 6; j++) if (lg[j] > best) { best = lg[j]; a = j; }
                const float vca   = vcs[a];
                const float delay = vca / bw[s] - 30000.0f;          // BUF
#pragma unroll
                for (int rr = 0; rr < 6; rr++) {                     // roll(-1, axis=1)
                    const float t0 = st[rr][0];
#pragma unroll
                    for (int j = 0; j < 7; j++) st[rr][j] = st[rr][j + 1];
                    st[rr][7] = t0;
                }
                const float VBR[6] = {300.f, 750.f, 1200.f, 1850.f, 2850.f, 4300.f};
                st[0][7] = VBR[a] / 4300.0f;
                st[1][7] = 3.0f;                                     // BUF/1000/10
                st[2][7] = vca / delay / 1000.0f;
                st[3][7] = delay / 1000.0f / 10.0f;
#pragma unroll
                for (int j = 0; j < 6; j++) st[4][j] = vcs[j] / 1000000.0f;
                st[5][7] = (7.0f - (float)s) / 8.0f;
            }
            __syncthreads();
        } else {
            if (bid == 0 && tid < 6) out[tid] = lg[tid];
        }
    }
}

extern "C" void kernel_launch(void* const* d_in, const int* in_sizes, int n_in,
                              void* d_out, int out_size)
{
    (void)in_sizes; (void)n_in; (void)out_size;
    actor_net_kernel<<<NBLK, NTHR>>>(
        (const float*)d_in[0],  (const float*)d_in[1],  (const float*)d_in[2],
        (const float*)d_in[3],  (const float*)d_in[4],  (const float*)d_in[5],
        (const float*)d_in[6],  (const float*)d_in[7],  (const float*)d_in[8],
        (const float*)d_in[9],  (const float*)d_in[10], (const float*)d_in[11],
        (const float*)d_in[12], (float*)d_out);
}

// round 7
// speedup vs baseline: 1.1043x; 1.1043x over previous
#include <cuda_runtime.h>

// ActorNetwork_mid_concat: 7 sequential tiny-MLP evaluations with argmax-driven
// state updates. Persistent 16-block kernel; w3 (128x2048) partitioned into
// 16 register-resident 128x128 slices; barrier-free cross-block partial
// exchange via monotonic release/acquire flags (graph-replay safe, no reset).
// Each block builds only ITS 128-wide slice of feat (segment boundaries are
// 128-aligned), and the gpu-scope MEMBAR is replaced by st.release/ld.acquire.

#define NBLK  16
#define NTHR  256
#define NSTEP 7

// Persistent device scratch (allowed: no allocation).
__device__ float    g_partial[2][NBLK][128];
__device__ unsigned g_flag[NBLK];   // cumulative step count per block (monotonic across launches)

__device__ __forceinline__ void st_release_u32(unsigned* p, unsigned v) {
    asm volatile("st.release.gpu.global.u32 [%0], %1;" :: "l"(p), "r"(v) : "memory");
}
__device__ __forceinline__ unsigned ld_acquire_u32(const unsigned* p) {
    unsigned v;
    asm volatile("ld.acquire.gpu.global.u32 %0, [%1];" : "=r"(v) : "l"(p) : "memory");
    return v;
}

__global__ __launch_bounds__(NTHR, 1)
void actor_net_kernel(const float* __restrict__ inp,
                      const float* __restrict__ conv_w, const float* __restrict__ conv_b,
                      const float* __restrict__ w0, const float* __restrict__ b0,
                      const float* __restrict__ w1, const float* __restrict__ b1,
                      const float* __restrict__ w2, const float* __restrict__ b2,
                      const float* __restrict__ w3, const float* __restrict__ b3,
                      const float* __restrict__ w4, const float* __restrict__ b4,
                      float* __restrict__ out)
{
    __shared__ __align__(16) float featb[128];       // this block's feat slice
    __shared__ float cw[128 * 4], cb[128];           // conv weights (conv blocks only)
    __shared__ float aw[128], ab[128];               // affine weights (bid 0/1/15 only)
    __shared__ float b3s[128];
    __shared__ float w4s[6 * 128], b4s[6];
    __shared__ float st[6][8], bw[8], vcs[6];
    __shared__ float hbuf[128], lg[6];
    __shared__ unsigned sbase;

    const int tid = threadIdx.x;
    const int bid = blockIdx.x;

    // ---- Prologue: only the small weights THIS block needs ----
    const bool is_conv = (bid >= 2 && bid <= 14);
    if (is_conv) {
        for (int i = tid; i < 512; i += NTHR) cw[i] = conv_w[i];
        if (tid < 128) cb[tid] = conv_b[tid];
    } else if (tid < 128) {
        if (bid == 0)       { aw[tid] = w0[tid]; ab[tid] = b0[tid]; }
        else if (bid == 1)  { aw[tid] = w1[tid]; ab[tid] = b1[tid]; }
        else                { aw[tid] = w2[tid]; ab[tid] = b2[tid]; }   // bid == 15
    }
    if (tid < 128) b3s[tid] = b3[tid];
    for (int i = tid; i < 768; i += NTHR) w4s[i] = w4[i];
    if (tid < 6)  b4s[tid] = b4[tid];
    if (tid < 48) st[tid >> 3][tid & 7] = inp[tid];
    if (tid >= 48 && tid < 56) bw[tid - 48] = inp[tid];
    if (tid < 6)  vcs[tid] = inp[56] * (float)(1 << tid);   // vs * {1,2,4,8,16,32}
    if (tid == 0) sbase = ld_acquire_u32(&g_flag[bid]);     // stable: only we write it

    // ---- w3 slice -> registers: thread t holds row r = t>>1, 64 cols (half = t&1) ----
    const int r    = tid >> 1;
    const int half = tid & 1;
    float4 W[16];
    const float4* w3row =
        reinterpret_cast<const float4*>(w3 + (size_t)r * 2048 + bid * 128 + half * 64);
#pragma unroll
    for (int i = 0; i < 16; i++) W[i] = __ldg(&w3row[i]);

    // Precompute this block's segment mapping (uniform per block).
    int seg_row = 0, seg_j0 = 0;
    if (bid >= 2 && bid <= 6)       { seg_row = 2; seg_j0 = (bid - 2)  * 128; }
    else if (bid >= 7 && bid <= 11) { seg_row = 3; seg_j0 = (bid - 7)  * 128; }
    else if (bid >= 12 && bid <= 14){ seg_row = 4; seg_j0 = (bid - 12) * 128; }

    __syncthreads();
    const unsigned base = sbase;

    for (int s = 0; s < NSTEP; ++s) {
        // ---- Phase A: build only this block's 128 feat values ----
        if (tid < 128) {
            float val;
            if (bid == 0) {
                val = fmaxf(fmaf(st[0][7], aw[tid], ab[tid]), 0.0f);          // s0
            } else if (bid == 1) {
                val = fmaxf(fmaf(st[1][7], aw[tid], ab[tid]), 0.0f);          // s1
            } else if (bid == 15) {
                val = fmaf(st[4][7], aw[tid], ab[tid]);                       // s5: no relu
            } else {
                const int j = seg_j0 + tid;
                int f, k;
                if (seg_row < 4) { f = j / 5; k = j - f * 5; }                // s2/s3: 5 windows
                else             { f = j / 3; k = j - f * 3; }                // s4:    3 windows
                float v = cb[f];
                v = fmaf(st[seg_row][k],     cw[f * 4 + 0], v);
                v = fmaf(st[seg_row][k + 1], cw[f * 4 + 1], v);
                v = fmaf(st[seg_row][k + 2], cw[f * 4 + 2], v);
                v = fmaf(st[seg_row][k + 3], cw[f * 4 + 3], v);
                val = fmaxf(v, 0.0f);
            }
            featb[tid] = val;
        }
        __syncthreads();

        // ---- Phase B: register-resident partial matvec for this block's slice ----
        const float4* fp = reinterpret_cast<const float4*>(featb + half * 64);
        float4 acc = make_float4(0.f, 0.f, 0.f, 0.f);
#pragma unroll
        for (int i = 0; i < 16; i++) {
            const float4 f4 = fp[i];
            acc.x = fmaf(W[i].x, f4.x, acc.x);
            acc.y = fmaf(W[i].y, f4.y, acc.y);
            acc.z = fmaf(W[i].z, f4.z, acc.z);
            acc.w = fmaf(W[i].w, f4.w, acc.w);
        }
        float p = (acc.x + acc.y) + (acc.z + acc.w);
        p += __shfl_xor_sync(0xffffffffu, p, 1);   // combine the two halves of row r

        const int buf = s & 1;
        if (half == 0) __stcg(&g_partial[buf][bid][r], p);
        __syncthreads();                            // all partial STGs issued
        const unsigned target = base + (unsigned)s + 1u;
        if (tid == 0) st_release_u32(&g_flag[bid], target);  // cumulative release

        // ---- Phase C: wait for all blocks' partials for this step ----
        if (tid < NBLK) {
            while ((int)(ld_acquire_u32(&g_flag[tid]) - target) < 0) { /* spin */ }
        }
        __syncthreads();

        // ---- Phase D: deterministic reduce -> h (every block, identical order) ----
        if (tid < 128) {
            float a = b3s[tid];
#pragma unroll
            for (int b = 0; b < NBLK; b++) a += __ldcg(&g_partial[buf][b][tid]);
            hbuf[tid] = fmaxf(a, 0.0f);
        }
        __syncthreads();

        // ---- Phase E: logits = w4 @ h + b4 (6 warps) ----
        if (tid < 192) {
            const int a = tid >> 5, l = tid & 31;
            float v = 0.0f;
            v = fmaf(w4s[a * 128 + l],      hbuf[l],      v);
            v = fmaf(w4s[a * 128 + l + 32], hbuf[l + 32], v);
            v = fmaf(w4s[a * 128 + l + 64], hbuf[l + 64], v);
            v = fmaf(w4s[a * 128 + l + 96], hbuf[l + 96], v);
#pragma unroll
            for (int o = 16; o > 0; o >>= 1) v += __shfl_down_sync(0xffffffffu, v, o);
            if (l == 0) lg[a] = v + b4s[a];
        }
        __syncthreads();

        // ---- Phase F: argmax + state update (exact reference arithmetic) ----
        if (s < 6) {
            if (tid == 0) {
                int   a    = 0;
                float best = lg[0];
#pragma unroll
                for (int j = 1; j < 6; j++) if (lg[j] > best) { best = lg[j]; a = j; }
                const float vca   = vcs[a];
                const float delay = vca / bw[s] - 30000.0f;          // BUF
#pragma unroll
                for (int rr = 0; rr < 6; rr++) {                     // roll(-1, axis=1)
                    const float t0 = st[rr][0];
#pragma unroll
                    for (int j = 0; j < 7; j++) st[rr][j] = st[rr][j + 1];
                    st[rr][7] = t0;
                }
                const float VBR[6] = {300.f, 750.f, 1200.f, 1850.f, 2850.f, 4300.f};
                st[0][7] = VBR[a] / 4300.0f;
                st[1][7] = 3.0f;                                     // BUF/1000/10
                st[2][7] = vca / delay / 1000.0f;
                st[3][7] = delay / 1000.0f / 10.0f;
#pragma unroll
                for (int j = 0; j < 6; j++) st[4][j] = vcs[j] / 1000000.0f;
                st[5][7] = (7.0f - (float)s) / 8.0f;
            }
            __syncthreads();
        } else {
            if (bid == 0 && tid < 6) out[tid] = lg[tid];
        }
    }
}

extern "C" void kernel_launch(void* const* d_in, const int* in_sizes, int n_in,
                              void* d_out, int out_size)
{
    (void)in_sizes; (void)n_in; (void)out_size;
    actor_net_kernel<<<NBLK, NTHR>>>(
        (const float*)d_in[0],  (const float*)d_in[1],  (const float*)d_in[2],
        (const float*)d_in[3],  (const float*)d_in[4],  (const float*)d_in[5],
        (const float*)d_in[6],  (const float*)d_in[7],  (const float*)d_in[8],
        (const float*)d_in[9],  (const float*)d_in[10], (const float*)d_in[11],
        (const float*)d_in[12], (float*)d_out);
}